// round 4
// baseline (speedup 1.0000x reference)
#include <cuda_runtime.h>
#include <cuda_bf16.h>

// EMD between two 8-point sets = min-cost perfect matching on the 8x8
// pairwise-distance matrix. Solved exactly with Held-Karp subset DP:
//   dp[mask] = min over j in mask of dp[mask ^ (1<<j)] + dist[popc(mask)-1][j]
// 256 states * <=8 transitions = 1024 min-adds per batch (vs 40320
// permutations in the reference). One warp per batch; DP levels (grouped by
// popcount) are parallelized across the 32 lanes with __syncwarp between
// levels. dp + dist live in per-warp shared memory.

#define WARPS_PER_BLOCK 8
#define THREADS_PER_BLOCK (WARPS_PER_BLOCK * 32)

__global__ void __launch_bounds__(THREADS_PER_BLOCK)
emd_assign_kernel(const float* __restrict__ pred,
                  const float* __restrict__ targ,
                  float* __restrict__ out, int B)
{
    __shared__ float s_dist[WARPS_PER_BLOCK][64];
    __shared__ float s_dp[WARPS_PER_BLOCK][256];
    __shared__ float s_pts[WARPS_PER_BLOCK][48];   // 24 pred + 24 target floats

    const int warp = threadIdx.x >> 5;
    const int lane = threadIdx.x & 31;
    const int b = blockIdx.x * WARPS_PER_BLOCK + warp;
    if (b >= B) return;

    float* P  = s_pts[warp];        // pred  [8][3]
    float* T  = s_pts[warp] + 24;   // targ  [8][3]
    float* d  = s_dist[warp];       // dist  [8][8] row-major (i = pred, j = targ)
    float* dp = s_dp[warp];

    // Load the 48 input floats for this batch (coalesced within the warp).
    const float* pb = pred + (size_t)b * 24;
    const float* tb = targ + (size_t)b * 24;
    if (lane < 24) {
        P[lane] = pb[lane];
        T[lane] = tb[lane];
    }
    __syncwarp();

    // Pairwise distances: each lane computes entries lane and lane+32.
#pragma unroll
    for (int r = 0; r < 2; ++r) {
        int e = lane + r * 32;
        int i = e >> 3;
        int j = e & 7;
        float dx = P[i * 3 + 0] - T[j * 3 + 0];
        float dy = P[i * 3 + 1] - T[j * 3 + 1];
        float dz = P[i * 3 + 2] - T[j * 3 + 2];
        d[e] = sqrtf(dx * dx + dy * dy + dz * dz);
    }
    if (lane == 0) dp[0] = 0.0f;
    __syncwarp();

    // Subset DP, level = popcount(mask). Masks with the same popcount are
    // independent; lane handles masks m = lane | (q<<5), q = 0..7.
#pragma unroll
    for (int k = 1; k <= 8; ++k) {
        const float* drow = d + (k - 1) * 8;
#pragma unroll
        for (int q = 0; q < 8; ++q) {
            int m = lane | (q << 5);
            if (__popc(m) == k) {
                float best = 3.4e38f;
                int mm = m;
                while (mm) {
                    int j = __ffs(mm) - 1;
                    mm &= mm - 1;
                    best = fminf(best, dp[m ^ (1 << j)] + drow[j]);
                }
                dp[m] = best;
            }
        }
        __syncwarp();
    }

    if (lane == 0) out[b] = dp[255];
}

extern "C" void kernel_launch(void* const* d_in, const int* in_sizes, int n_in,
                              void* d_out, int out_size)
{
    const float* pred = (const float*)d_in[0];
    const float* targ = (const float*)d_in[1];
    float* out = (float*)d_out;
    int B = in_sizes[0] / 24;   // [B, 8, 3] float32
    int grid = (B + WARPS_PER_BLOCK - 1) / WARPS_PER_BLOCK;
    emd_assign_kernel<<<grid, THREADS_PER_BLOCK>>>(pred, targ, out, B);
}

// round 7
// speedup vs baseline: 1.4289x; 1.4289x over previous
#include <cuda_runtime.h>
#include <cuda_bf16.h>

// EMD between two 8-point sets = min-cost perfect matching on the 8x8
// pairwise-distance matrix, solved with Held-Karp subset DP:
//   dp[mask] = min over j in mask of dp[mask ^ (1<<j)] + dist[popc(mask)-1][j]
//
// One warp per batch. Masks are processed level-by-level (level = popcount)
// using a compile-time table of masks SORTED BY POPCOUNT, so at level k lane l
// handles mask ord[off(k) + l] (plus a +32 slot for levels with >32 masks).
// Every lane in a slot is at the same level (no divergence) and every
// transition chain has compile-time length k (fully unrolled, no branches).
// Level 1 is a direct copy of dist row 0; level 8 (single mask 0xFF) is
// parallelized over 8 lanes + butterfly min-reduce.

#define WARPS_PER_BLOCK 8
#define THREADS_PER_BLOCK (WARPS_PER_BLOCK * 32)

// ---- compile-time mask table ordered by popcount --------------------------
constexpr int cpc(int m) { int c = 0; for (int i = 0; i < 8; ++i) c += (m >> i) & 1; return c; }
struct Tab { unsigned char ord[256]; };
constexpr Tab mkTab() {
    Tab t{}; int idx = 0;
    for (int k = 0; k <= 8; ++k)
        for (int m = 0; m < 256; ++m)
            if (cpc(m) == k) t.ord[idx++] = (unsigned char)m;
    return t;
}
__constant__ Tab TAB = mkTab();

// off(k) = first index of masks with popcount k; counts: 1,8,28,56,70,56,28,8,1
__host__ __device__ constexpr int OFF(int k) {
    return (k == 0) ? 0 : (k == 1) ? 1 : (k == 2) ? 9 : (k == 3) ? 37 :
           (k == 4) ? 93 : (k == 5) ? 163 : (k == 6) ? 219 : (k == 7) ? 247 :
           (k == 8) ? 255 : 256;
}

__global__ void __launch_bounds__(THREADS_PER_BLOCK)
emd_assign_kernel(const float4* __restrict__ pred4,
                  const float4* __restrict__ targ4,
                  float* __restrict__ out, int B)
{
    __shared__ float  s_dist[WARPS_PER_BLOCK][64];
    __shared__ float  s_dp  [WARPS_PER_BLOCK][256];
    __shared__ float4 s_pts [WARPS_PER_BLOCK][12];   // 6 pred + 6 targ float4s

    const int warp = threadIdx.x >> 5;
    const int lane = threadIdx.x & 31;
    const int b = blockIdx.x * WARPS_PER_BLOCK + warp;
    if (b >= B) return;

    float* d  = s_dist[warp];
    float* dp = s_dp[warp];
    float* P  = (float*)s_pts[warp];   // floats 0..23  = pred [8][3]
    float* T  = P + 24;                // floats 24..47 = targ [8][3]

    // Vectorized input load: 12 float4 per batch (24 floats pred + 24 targ).
    if (lane < 6)       s_pts[warp][lane] = pred4[(size_t)b * 6 + lane];
    else if (lane < 12) s_pts[warp][lane] = targ4[(size_t)b * 6 + (lane - 6)];
    __syncwarp();

    // Pairwise distances: entry e = i*8+j; each lane computes e and e+32.
#pragma unroll
    for (int r = 0; r < 2; ++r) {
        int e = lane + r * 32;
        int i = e >> 3;
        int j = e & 7;
        float dx = P[i * 3 + 0] - T[j * 3 + 0];
        float dy = P[i * 3 + 1] - T[j * 3 + 1];
        float dz = P[i * 3 + 2] - T[j * 3 + 2];
        d[e] = sqrtf(dx * dx + dy * dy + dz * dz);
    }
    __syncwarp();

    // Level 1: dp[1<<j] = dist[0][j]  (pred 0 matched to target j).
    if (lane < 8) dp[1 << lane] = d[lane];
    __syncwarp();

    // Levels 2..7: dense lane assignment from the popcount-ordered table.
#pragma unroll
    for (int k = 2; k <= 7; ++k) {
        const float* drow = d + (k - 1) * 8;
        const int cnt = OFF(k + 1) - OFF(k);
        const int slots = (cnt + 31) / 32;
#pragma unroll
        for (int s = 0; s < slots; ++s) {
            int idx = lane + s * 32;
            if (idx < cnt) {
                int m = TAB.ord[OFF(k) + idx];
                float best = 3.4e38f;
                int mm = m;
#pragma unroll
                for (int t = 0; t < k; ++t) {          // exactly k set bits
                    int j = __ffs(mm) - 1;
                    mm &= mm - 1;
                    best = fminf(best, dp[m ^ (1 << j)] + drow[j]);
                }
                dp[m] = best;
            }
        }
        __syncwarp();
    }

    // Level 8 (mask 0xFF): 8 candidates in parallel + butterfly min-reduce.
    float cand = 3.4e38f;
    if (lane < 8) cand = dp[255 ^ (1 << lane)] + d[56 + lane];
    cand = fminf(cand, __shfl_xor_sync(0xffffffffu, cand, 4));
    cand = fminf(cand, __shfl_xor_sync(0xffffffffu, cand, 2));
    cand = fminf(cand, __shfl_xor_sync(0xffffffffu, cand, 1));
    if (lane == 0) out[b] = cand;
}

extern "C" void kernel_launch(void* const* d_in, const int* in_sizes, int n_in,
                              void* d_out, int out_size)
{
    const float4* pred = (const float4*)d_in[0];
    const float4* targ = (const float4*)d_in[1];
    float* out = (float*)d_out;
    int B = in_sizes[0] / 24;   // [B, 8, 3] float32
    int grid = (B + WARPS_PER_BLOCK - 1) / WARPS_PER_BLOCK;
    emd_assign_kernel<<<grid, THREADS_PER_BLOCK>>>(pred, targ, out, B);
}

// round 9
// speedup vs baseline: 2.0590x; 1.4410x over previous
#include <cuda_runtime.h>
#include <cuda_bf16.h>

// EMD between two 8-point sets = min-cost perfect matching on the 8x8
// pairwise-distance matrix, solved with Held-Karp subset DP entirely in
// registers + warp shuffles.
//
// Mask -> (lane, reg) mapping:  lane = mask & 31 (bits 0..4),
//                               q    = mask >> 5 (bits 5..7, regs dp[0..7]).
// Transition dp[m ^ (1<<j)]:
//   j in [0,5): partner lane lane^(1<<j), same reg  -> one __shfl_xor_sync
//   j in [5,8): same lane, reg q^(1<<(j-5))         -> local register
// Levels (popcount) run sequentially; within a level all (k,q) pairs are
// straight-line predicated code. Each dp slot is written exactly once (at
// level popc(mask)), so shuffle partners always carry level-(k-1) values.
// No shared-memory dp, no __syncwarp in the DP, no lookup tables (the old
// divergent-index __constant__ loads serialized into per-lane replays).

#define WARPS_PER_BLOCK 8
#define THREADS_PER_BLOCK (WARPS_PER_BLOCK * 32)

__host__ __device__ constexpr int PC3(int q) { return ((q >> 0) & 1) + ((q >> 1) & 1) + ((q >> 2) & 1); }

__global__ void __launch_bounds__(THREADS_PER_BLOCK)
emd_assign_kernel(const float4* __restrict__ pred4,
                  const float4* __restrict__ targ4,
                  float* __restrict__ out, int B)
{
    __shared__ float  s_dist[WARPS_PER_BLOCK][64];
    __shared__ float4 s_pts [WARPS_PER_BLOCK][12];   // 6 pred + 6 targ float4s

    const int warp = threadIdx.x >> 5;
    const int lane = threadIdx.x & 31;
    const int b = blockIdx.x * WARPS_PER_BLOCK + warp;
    if (b >= B) return;

    float* d = s_dist[warp];
    float* P = (float*)s_pts[warp];   // floats 0..23  = pred [8][3]
    float* T = P + 24;                // floats 24..47 = targ [8][3]

    // Vectorized input load: 12 float4 per batch.
    if (lane < 6)       s_pts[warp][lane] = pred4[(size_t)b * 6 + lane];
    else if (lane < 12) s_pts[warp][lane] = targ4[(size_t)b * 6 + (lane - 6)];
    __syncwarp();

    // Pairwise distances: entry e = i*8+j (i = pred, j = targ); 2 per lane.
#pragma unroll
    for (int r = 0; r < 2; ++r) {
        int e = lane + r * 32;
        int i = e >> 3;
        int j = e & 7;
        float dx = P[i * 3 + 0] - T[j * 3 + 0];
        float dy = P[i * 3 + 1] - T[j * 3 + 1];
        float dz = P[i * 3 + 2] - T[j * 3 + 2];
        d[e] = sqrtf(dx * dx + dy * dy + dz * dz);
    }
    __syncwarp();

    // Register-resident dp. +INF everywhere except mask 0 (lane 0, q 0) = 0.
    const float INF = __int_as_float(0x7f800000);
    float dp[8];
#pragma unroll
    for (int q = 0; q < 8; ++q) dp[q] = INF;
    if (lane == 0) dp[0] = 0.0f;

    // Hoisted lane-derived predicates (reused across all levels).
    const bool p0 = (lane & 1)  != 0;
    const bool p1 = (lane & 2)  != 0;
    const bool p2 = (lane & 4)  != 0;
    const bool p3 = (lane & 8)  != 0;
    const bool p4 = (lane & 16) != 0;
    const int  pc5 = __popc(lane);

#pragma unroll
    for (int k = 1; k <= 8; ++k) {
        // Uniform-address LDS broadcasts of dist row k-1 (off the DP chain).
        float dr[8];
#pragma unroll
        for (int j = 0; j < 8; ++j) dr[j] = d[(k - 1) * 8 + j];

#pragma unroll
        for (int q = 0; q < 8; ++q) {
            const int need = k - PC3(q);          // popc5(lane) of active lanes
            if (need < 0 || need > 5) continue;   // compile-time prune

            // Cross-lane neighbors (full-warp shuffles; partners with popc k-1
            // hold final level-(k-1) values, popc k+1 partners are still INF
            // and excluded by the lane-bit predicate).
            float nb0 = __shfl_xor_sync(0xffffffffu, dp[q], 1);
            float nb1 = __shfl_xor_sync(0xffffffffu, dp[q], 2);
            float nb2 = __shfl_xor_sync(0xffffffffu, dp[q], 4);
            float nb3 = __shfl_xor_sync(0xffffffffu, dp[q], 8);
            float nb4 = __shfl_xor_sync(0xffffffffu, dp[q], 16);

            float best = INF;
            best = p0 ? fminf(best, nb0 + dr[0]) : best;
            best = p1 ? fminf(best, nb1 + dr[1]) : best;
            best = p2 ? fminf(best, nb2 + dr[2]) : best;
            best = p3 ? fminf(best, nb3 + dr[3]) : best;
            best = p4 ? fminf(best, nb4 + dr[4]) : best;
            // Register-local transitions for mask bits 5..7 (compile-time).
            if (q & 1) best = fminf(best, dp[q ^ 1] + dr[5]);
            if (q & 2) best = fminf(best, dp[q ^ 2] + dr[6]);
            if (q & 4) best = fminf(best, dp[q ^ 4] + dr[7]);

            // Write back only on the lane's own level (select, not branch).
            dp[q] = (pc5 == need) ? best : dp[q];
        }
    }

    // Answer = dp[mask 255] = lane 31, reg 7.
    if (lane == 31) out[b] = dp[7];
}

extern "C" void kernel_launch(void* const* d_in, const int* in_sizes, int n_in,
                              void* d_out, int out_size)
{
    const float4* pred = (const float4*)d_in[0];
    const float4* targ = (const float4*)d_in[1];
    float* out = (float*)d_out;
    int B = in_sizes[0] / 24;   // [B, 8, 3] float32
    int grid = (B + WARPS_PER_BLOCK - 1) / WARPS_PER_BLOCK;
    emd_assign_kernel<<<grid, THREADS_PER_BLOCK>>>(pred, targ, out, B);
}